// round 2
// baseline (speedup 1.0000x reference)
#include <cuda_runtime.h>
#include <math.h>

#define Hh   64
#define Ww   192
#define HW   12288
#define Wp   194
#define Pp   12804      // (64+2)*(192+2)
#define CIN  256
#define COUT 128
#define LEAK 0.01f
#define EPSV 1e-5f

// ---------------- scratch (device globals; no allocation allowed) ----------
__device__ float g_xpad[CIN * Pp];    // padded input, per channel
__device__ float g_Y[CIN * HW];       // stage-1 gather output
__device__ float g_Z[COUT * HW];      // pre-BN linear outputs (reused)
__device__ float g_T[COUT * HW];      // depthwise outputs (reused)
__device__ float g_sc[COUT];          // BN scale  (g * rsqrt(var+eps))
__device__ float g_sh[COUT];          // BN shift  (b - mu*scale)

// ---------------- pad ------------------------------------------------------
__global__ void k_pad(const float* __restrict__ x) {
    int i = blockIdx.x * 256 + threadIdx.x;
    if (i >= CIN * Pp) return;
    int c = i / Pp, pp = i - c * Pp;
    int pr = pp / Wp, pc = pp - pr * Wp;
    float v = 0.f;
    if (pr >= 1 && pr <= Hh && pc >= 1 && pc <= Ww)
        v = x[c * HW + (pr - 1) * Ww + (pc - 1)];
    g_xpad[i] = v;
}

// ---------------- stage-1 deformable gather --------------------------------
// grid (HW/128, CIN/8), block 128. Each thread: one pixel, 8 channels.
__global__ __launch_bounds__(128) void k_gather(const float* __restrict__ xr,
                                                const float* __restrict__ ro) {
    int p = blockIdx.x * 128 + threadIdx.x;
    int cbase = blockIdx.y * 8;
    int r = p / Ww, q = p - r * Ww;
    float v = (float)((r + 1) * Wp + (q + 1));
    float o = 3.f / (1.f + expf(-xr[p]));

    int   idx[9][4];
    float wgt[9][4];
    const float PM1 = (float)(Pp - 1);
#pragma unroll
    for (int k = 0; k < 9; k++) {
        float xo = (float)(k % 3 - 1);
        float d  = (float)((k / 3 - 1) * Wp);
        float pre   = v + xo + d;
        float offv  = __fadd_rn(__fmul_rn(o, xo), d);   // mul then add, no FMA
        float after = pre + offv;
        float fo = floorf(offv), co = ceilf(offv);
        float avf  = fminf(fmaxf(pre + fo, 0.f), PM1);
        float avf1 = fminf(fmaxf(avf + xo, 0.f), PM1);
        float avc  = fminf(fmaxf(pre + co, 0.f), PM1);
        float avc1 = fminf(fmaxf(avc + xo, 0.f), PM1);
        float a1 = fabsf((after - avf)  / (float)Wp);
        float a2 = fabsf((avc1 - after) / (float)Wp);
        wgt[k][0] = a1 * fabsf(after - avf);
        wgt[k][1] = a1 * fabsf(avf1 - after);
        wgt[k][2] = a2 * fabsf(avc - after);
        wgt[k][3] = a2 * fabsf(after - avc1);
        idx[k][0] = (int)avf;  idx[k][1] = (int)avf1;
        idx[k][2] = (int)avc;  idx[k][3] = (int)avc1;
    }

    for (int j = 0; j < 8; j++) {
        int c = cbase + j;
        const float* xp = g_xpad + c * Pp;
        const float* rr = ro + c * 9;
        float acc = 0.f;
#pragma unroll
        for (int k = 0; k < 9; k++) {
            float s = wgt[k][0] * __ldg(xp + idx[k][0])
                    + wgt[k][1] * __ldg(xp + idx[k][1])
                    + wgt[k][2] * __ldg(xp + idx[k][2])
                    + wgt[k][3] * __ldg(xp + idx[k][3]);
            acc += rr[k] * s;
        }
        g_Y[c * HW + p] = acc;
    }
}

// ---------------- SIMT GEMM: Z[o,p] = sum_c W[o,c] * X[c,p] ----------------
// tile 64(o) x 64(p), 256 threads, 4x4 microtile, K chunks of 16
__global__ __launch_bounds__(256) void k_gemm(const float* __restrict__ Wm,
                                              const float* __restrict__ X,
                                              float* __restrict__ Z, int K) {
    __shared__ float As[16][64];
    __shared__ float Bs[16][64];
    int obase = blockIdx.y * 64, pbase = blockIdx.x * 64;
    int tid = threadIdx.x;
    int lo  = tid >> 2;            // 0..63  (A load row)
    int lk4 = (tid & 3) * 4;       // A load k quad
    int bk  = tid >> 4;            // 0..15  (B load k)
    int bp  = (tid & 15) * 4;      // B load p quad
    int to  = tid >> 4;            // compute: o-group 0..15
    int tp  = tid & 15;            // compute: p-group 0..15
    float acc[4][4] = {};

    for (int kc = 0; kc < K; kc += 16) {
        float4 av = *(const float4*)(Wm + (obase + lo) * K + kc + lk4);
        As[lk4 + 0][lo] = av.x; As[lk4 + 1][lo] = av.y;
        As[lk4 + 2][lo] = av.z; As[lk4 + 3][lo] = av.w;
        float4 bv = *(const float4*)(X + (kc + bk) * HW + pbase + bp);
        *(float4*)&Bs[bk][bp] = bv;
        __syncthreads();
#pragma unroll
        for (int kk = 0; kk < 16; kk++) {
            float4 a = *(const float4*)&As[kk][to * 4];
            float4 b = *(const float4*)&Bs[kk][tp * 4];
            acc[0][0] += a.x * b.x; acc[0][1] += a.x * b.y; acc[0][2] += a.x * b.z; acc[0][3] += a.x * b.w;
            acc[1][0] += a.y * b.x; acc[1][1] += a.y * b.y; acc[1][2] += a.y * b.z; acc[1][3] += a.y * b.w;
            acc[2][0] += a.z * b.x; acc[2][1] += a.z * b.y; acc[2][2] += a.z * b.z; acc[2][3] += a.z * b.w;
            acc[3][0] += a.w * b.x; acc[3][1] += a.w * b.y; acc[3][2] += a.w * b.z; acc[3][3] += a.w * b.w;
        }
        __syncthreads();
    }
#pragma unroll
    for (int i = 0; i < 4; i++) {
        float4 w4 = make_float4(acc[i][0], acc[i][1], acc[i][2], acc[i][3]);
        *(float4*)(Z + (obase + to * 4 + i) * HW + pbase + tp * 4) = w4;
    }
}

// ---------------- BN stats -> scale/shift ----------------------------------
__global__ void k_stats(const float* __restrict__ Z, const float* __restrict__ g,
                        const float* __restrict__ b) {
    int c = blockIdx.x;
    const float* z = Z + c * HW;
    float s = 0.f, s2 = 0.f;
    for (int i = threadIdx.x; i < HW; i += 256) {
        float v = z[i]; s += v; s2 += v * v;
    }
    __shared__ float ss[256], ss2[256];
    ss[threadIdx.x] = s; ss2[threadIdx.x] = s2;
    __syncthreads();
    for (int st = 128; st > 0; st >>= 1) {
        if (threadIdx.x < st) {
            ss[threadIdx.x]  += ss[threadIdx.x + st];
            ss2[threadIdx.x] += ss2[threadIdx.x + st];
        }
        __syncthreads();
    }
    if (threadIdx.x == 0) {
        float mu  = ss[0] / (float)HW;
        float var = ss2[0] / (float)HW - mu * mu;
        float rs  = rsqrtf(var + EPSV);
        float sc  = g[c] * rs;
        g_sc[c] = sc;
        g_sh[c] = b[c] - mu * sc;
    }
}

// ---------------- depthwise 3x3 on act(Z) ----------------------------------
// grid (HW/256, COUT), block 256
__global__ void k_dw(const float* __restrict__ Z, const float* __restrict__ dwz,
                     float* __restrict__ T) {
    int c = blockIdx.y;
    int p = blockIdx.x * 256 + threadIdx.x;
    int r = p / Ww, q = p - r * Ww;
    float sc = g_sc[c], sh = g_sh[c];
    const float* z = Z + c * HW;
    float acc = 0.f;
#pragma unroll
    for (int ky = 0; ky < 3; ky++) {
#pragma unroll
        for (int kx = 0; kx < 3; kx++) {
            int rr = r + ky - 1, qq = q + kx - 1;
            if (rr >= 0 && rr < Hh && qq >= 0 && qq < Ww) {
                float v = z[rr * Ww + qq] * sc + sh;
                v = (v >= 0.f) ? v : LEAK * v;
                acc += dwz[c * 9 + ky * 3 + kx] * v;
            }
        }
    }
    T[c * HW + p] = acc;
}

// ---------------- final BN+leaky apply -------------------------------------
__global__ void k_apply(const float* __restrict__ Z, float* __restrict__ out) {
    int i = blockIdx.x * 256 + threadIdx.x;
    if (i >= COUT * HW) return;
    int c = i / HW;
    float v = Z[i] * g_sc[c] + g_sh[c];
    out[i] = (v >= 0.f) ? v : LEAK * v;
}

// ---------------- launch ----------------------------------------------------
extern "C" void kernel_launch(void* const* d_in, const int* in_sizes, int n_in,
                              void* d_out, int out_size) {
    const float* x    = (const float*)d_in[0];
    const float* xr   = (const float*)d_in[1];
    const float* ro   = (const float*)d_in[2];
    const float* wr   = (const float*)d_in[3];
    const float* gr   = (const float*)d_in[4];
    const float* br   = (const float*)d_in[5];
    const float* dw1  = (const float*)d_in[6];
    const float* pw1  = (const float*)d_in[7];
    const float* g1   = (const float*)d_in[8];
    const float* b1   = (const float*)d_in[9];
    const float* dw2  = (const float*)d_in[10];
    const float* pw2  = (const float*)d_in[11];
    const float* g2   = (const float*)d_in[12];
    const float* b2   = (const float*)d_in[13];
    float* out = (float*)d_out;

    float *pY, *pZ, *pT;
    cudaGetSymbolAddress((void**)&pY, g_Y);
    cudaGetSymbolAddress((void**)&pZ, g_Z);
    cudaGetSymbolAddress((void**)&pT, g_T);

    // pad
    k_pad<<<(CIN * Pp + 255) / 256, 256>>>(x);
    // stage 1: deformable gather -> Y (256 x HW)
    k_gather<<<dim3(HW / 128, CIN / 8), 128>>>(xr, ro);
    // reduce: Z1 = Wr @ Y
    k_gemm<<<dim3(HW / 64, COUT / 64), 256>>>(wr, pY, pZ, CIN);
    k_stats<<<COUT, 256>>>(pZ, gr, br);
    // block 1
    k_dw<<<dim3(HW / 256, COUT), 256>>>(pZ, dw1, pT);
    k_gemm<<<dim3(HW / 64, COUT / 64), 256>>>(pw1, pT, pZ, COUT);
    k_stats<<<COUT, 256>>>(pZ, g1, b1);
    // block 2
    k_dw<<<dim3(HW / 256, COUT), 256>>>(pZ, dw2, pT);
    k_gemm<<<dim3(HW / 64, COUT / 64), 256>>>(pw2, pT, pZ, COUT);
    k_stats<<<COUT, 256>>>(pZ, g2, b2);
    // final
    k_apply<<<(COUT * HW + 255) / 256, 256>>>(pZ, out);
}